// round 1
// baseline (speedup 1.0000x reference)
#include <cuda_runtime.h>
#include <math.h>

// ---------------------------------------------------------------------------
// Problem constants
// ---------------------------------------------------------------------------
#define B_   2
#define BS_  1024
#define WS_  512
#define DIN  2048
#define H_   16
#define DH_  128
#define DM_  2048
#define DFF_ 8192
#define TOK  (B_*BS_)        // 2048 query tokens
#define KVL  (WS_+BS_)       // 1536 kv length
#define KVTOK (B_*KVL)       // 3072 kv rows

// ---------------------------------------------------------------------------
// Scratch buffers (device globals; no runtime allocation allowed)
// ---------------------------------------------------------------------------
__device__ float g_xn  [TOK*DIN];
__device__ float g_qpre[TOK*DM_];
__device__ float g_kpre[TOK*DM_];
__device__ float g_vnew[TOK*DM_];
__device__ float g_qr  [TOK*DM_];
__device__ float g_kr  [KVTOK*DM_];
__device__ float g_vf  [KVTOK*DM_];
__device__ float g_qh  [TOK*DM_];
__device__ float g_kh  [KVTOK*DM_];
__device__ float g_vh  [KVTOK*DM_];
__device__ float g_ao  [TOK*DM_];
__device__ float g_op  [TOK*DM_];
__device__ float g_ln2 [TOK*DM_];
__device__ float g_ff  [TOK*DFF_];

// ---------------------------------------------------------------------------
// Row statistics helper for LayerNorm (block = 256 threads, one row)
// ---------------------------------------------------------------------------
__device__ __forceinline__ void row_stats_256(const float* __restrict__ row, int D,
                                              float& mean, float& inv) {
    const int tid = threadIdx.x;
    float s = 0.f, s2 = 0.f;
    for (int d = tid; d < D; d += 256) {
        float v = row[d];
        s += v;
        s2 = fmaf(v, v, s2);
    }
    #pragma unroll
    for (int o = 16; o; o >>= 1) {
        s  += __shfl_xor_sync(0xffffffffu, s,  o);
        s2 += __shfl_xor_sync(0xffffffffu, s2, o);
    }
    __shared__ float ws[8], ws2[8], out2[2];
    if ((tid & 31) == 0) { ws[tid >> 5] = s; ws2[tid >> 5] = s2; }
    __syncthreads();
    if (tid == 0) {
        float a = 0.f, b2 = 0.f;
        #pragma unroll
        for (int w = 0; w < 8; w++) { a += ws[w]; b2 += ws2[w]; }
        out2[0] = a; out2[1] = b2;
    }
    __syncthreads();
    mean = out2[0] / (float)D;
    float var = out2[1] / (float)D - mean * mean;
    inv = rsqrtf(var + 1e-5f);
}

// ---------------------------------------------------------------------------
// Plain LayerNorm: out = (x - mean)/sqrt(var+eps) * g
// ---------------------------------------------------------------------------
__global__ void __launch_bounds__(256) ln_kernel(const float* __restrict__ in,
                                                 const float* __restrict__ g,
                                                 float* __restrict__ out, int D) {
    const float* row = in + (size_t)blockIdx.x * D;
    float* orow = out + (size_t)blockIdx.x * D;
    float mean, inv;
    row_stats_256(row, D, mean, inv);
    for (int d = threadIdx.x; d < D; d += 256)
        orow[d] = (row[d] - mean) * inv * g[d];
}

// ---------------------------------------------------------------------------
// LN + RoPE for Q: rows are (b,i) over B*BS. rope row = WS + i, scale = xscale.
// ---------------------------------------------------------------------------
__global__ void __launch_bounds__(256) ln_rope_q_kernel(
    const float* __restrict__ in, const float* __restrict__ g,
    const float* __restrict__ rotary, const float* __restrict__ xscale,
    float* __restrict__ out) {
    const int r = blockIdx.x;           // 0..TOK-1
    const int i = r & (BS_ - 1);
    const int rp = WS_ + i;
    const float* row = in + (size_t)r * DM_;
    float* orow = out + (size_t)r * DM_;
    const float* fr = rotary + (size_t)rp * DM_;
    const float* sr = xscale + (size_t)rp * DM_;
    float mean, inv;
    row_stats_256(row, DM_, mean, inv);
    for (int t = threadIdx.x; t < DM_ / 2; t += 256) {
        int d0 = 2 * t;
        float x0 = (row[d0]     - mean) * inv * g[d0];
        float x1 = (row[d0 + 1] - mean) * inv * g[d0 + 1];
        float c0, s0, c1, s1;
        sincosf(fr[d0], &s0, &c0);
        sincosf(fr[d0 + 1], &s1, &c1);
        float sc0 = sr[d0], sc1 = sr[d0 + 1];
        orow[d0]     = (x0 * c0 - x1 * s0) * sc0;
        orow[d0 + 1] = (x1 * c1 + x0 * s1) * sc1;
    }
}

// ---------------------------------------------------------------------------
// LN + RoPE for K (with cache concat): rows (b,j) over B*KVL.
//   j <  WS: source = cache_k (no LN).  j >= WS: source = LN(k_pre).
//   rope row = j, scale = 1/xscale[j].
// ---------------------------------------------------------------------------
__global__ void __launch_bounds__(256) ln_rope_k_kernel(
    const float* __restrict__ kpre, const float* __restrict__ cache_k,
    const float* __restrict__ g, const float* __restrict__ rotary,
    const float* __restrict__ xscale, float* __restrict__ out) {
    const int rr = blockIdx.x;          // 0..KVTOK-1
    const int b = rr / KVL;
    const int j = rr - b * KVL;
    const bool doln = (j >= WS_);
    const float* row = doln ? (kpre + ((size_t)b * BS_ + (j - WS_)) * DM_)
                            : (cache_k + ((size_t)b * WS_ + j) * DM_);
    float mean = 0.f, inv = 1.f;
    if (doln) row_stats_256(row, DM_, mean, inv);
    const float* fr = rotary + (size_t)j * DM_;
    const float* sr = xscale + (size_t)j * DM_;
    float* orow = out + (size_t)rr * DM_;
    for (int t = threadIdx.x; t < DM_ / 2; t += 256) {
        int d0 = 2 * t;
        float x0 = row[d0], x1 = row[d0 + 1];
        if (doln) {
            x0 = (x0 - mean) * inv * g[d0];
            x1 = (x1 - mean) * inv * g[d0 + 1];
        }
        float c0, s0, c1, s1;
        sincosf(fr[d0], &s0, &c0);
        sincosf(fr[d0 + 1], &s1, &c1);
        float sc0 = 1.0f / sr[d0], sc1 = 1.0f / sr[d0 + 1];
        orow[d0]     = (x0 * c0 - x1 * s0) * sc0;
        orow[d0 + 1] = (x1 * c1 + x0 * s1) * sc1;
    }
}

// ---------------------------------------------------------------------------
// V concat: rows (b,j); j<WS -> cache_v else new v.
// ---------------------------------------------------------------------------
__global__ void __launch_bounds__(256) concat_v_kernel(
    const float* __restrict__ vnew, const float* __restrict__ cache_v,
    float* __restrict__ out) {
    const int rr = blockIdx.x;
    const int b = rr / KVL;
    const int j = rr - b * KVL;
    const float* src = (j < WS_) ? (cache_v + ((size_t)b * WS_ + j) * DM_)
                                 : (vnew + ((size_t)b * BS_ + (j - WS_)) * DM_);
    float* dst = out + (size_t)rr * DM_;
    for (int t = threadIdx.x; t < DM_ / 4; t += 256)
        ((float4*)dst)[t] = ((const float4*)src)[t];
}

// ---------------------------------------------------------------------------
// Tiled fp32 GEMM:  C[M,N] = A[M,K] * B[N,K]^T (+bias, optional relu)
// BM=BN=128, BK=8, 256 threads, 8x8 per thread.
// M % 128 == 0, N % 128 == 0, K % 8 == 0 (all true here).
// ---------------------------------------------------------------------------
__global__ void __launch_bounds__(256) gemm_nt_kernel(
    const float* __restrict__ A, const float* __restrict__ B,
    const float* __restrict__ bias, float* __restrict__ C,
    int M, int N, int K, int relu) {
    __shared__ float As[8][128];
    __shared__ float Bs[8][128];
    const int bm = blockIdx.y << 7;
    const int bn = blockIdx.x << 7;
    const int tid = threadIdx.x;
    const int lrow = tid >> 1;
    const int lcol = (tid & 1) << 2;
    const int trow = (tid >> 4) << 3;
    const int tcol = (tid & 15) << 3;
    const float* Ag = A + (size_t)(bm + lrow) * K + lcol;
    const float* Bg = B + (size_t)(bn + lrow) * K + lcol;
    float acc[8][8];
    #pragma unroll
    for (int i = 0; i < 8; i++)
        #pragma unroll
        for (int j = 0; j < 8; j++) acc[i][j] = 0.f;

    for (int k0 = 0; k0 < K; k0 += 8) {
        float4 a = *(const float4*)(Ag + k0);
        float4 b = *(const float4*)(Bg + k0);
        As[lcol + 0][lrow] = a.x; As[lcol + 1][lrow] = a.y;
        As[lcol + 2][lrow] = a.z; As[lcol + 3][lrow] = a.w;
        Bs[lcol + 0][lrow] = b.x; Bs[lcol + 1][lrow] = b.y;
        Bs[lcol + 2][lrow] = b.z; Bs[lcol + 3][lrow] = b.w;
        __syncthreads();
        #pragma unroll
        for (int kk = 0; kk < 8; kk++) {
            float ar[8], br[8];
            *(float4*)&ar[0] = *(const float4*)&As[kk][trow];
            *(float4*)&ar[4] = *(const float4*)&As[kk][trow + 4];
            *(float4*)&br[0] = *(const float4*)&Bs[kk][tcol];
            *(float4*)&br[4] = *(const float4*)&Bs[kk][tcol + 4];
            #pragma unroll
            for (int i = 0; i < 8; i++)
                #pragma unroll
                for (int j = 0; j < 8; j++)
                    acc[i][j] = fmaf(ar[i], br[j], acc[i][j]);
        }
        __syncthreads();
    }

    #pragma unroll
    for (int i = 0; i < 8; i++) {
        float* crow = C + (size_t)(bm + trow + i) * N + bn + tcol;
        #pragma unroll
        for (int jj = 0; jj < 2; jj++) {
            float4 v;
            float* vv = &v.x;
            #pragma unroll
            for (int j = 0; j < 4; j++) {
                float val = acc[i][jj * 4 + j];
                if (bias) val += bias[bn + tcol + jj * 4 + j];
                if (relu) val = fmaxf(val, 0.f);
                vv[j] = val;
            }
            *(float4*)(crow + jj * 4) = v;
        }
    }
}

// ---------------------------------------------------------------------------
// Banded flash attention.
// Query i attends to keys j with i < j <= i+WS (exactly 512 keys).
// grid: (BS/64, B*H), block 256.
// Dynamic smem layout (floats):
//   Qs  [128][64]  (d-major)                 8192
//   KVs [128][64] K^T  /  [64][128] V        8192
//   SP  [64][65]                             4160
//   ms/ls/osc  64 each                        192
// ---------------------------------------------------------------------------
#define ATTN_SMEM_FLOATS (8192 + 8192 + 4160 + 192)

__global__ void __launch_bounds__(256) attn_kernel(
    const float* __restrict__ QH, const float* __restrict__ KH,
    const float* __restrict__ VH, float* __restrict__ O) {
    extern __shared__ float sm[];
    float* Qs  = sm;
    float* KVs = sm + 8192;
    float* SP  = sm + 16384;
    float* ms  = SP + 64 * 65;
    float* ls  = ms + 64;
    float* osc = ls + 64;

    const int bh = blockIdx.y;
    const int b = bh >> 4, h = bh & 15;
    const int i0 = blockIdx.x << 6;
    const int tid = threadIdx.x;
    const int qb = (tid >> 4) << 2;    // query base (both phases)
    const int kb = (tid & 15) << 2;    // key base (S phase)
    const int db = (tid & 15) << 3;    // dim base (PV phase)

    // load Q tile transposed
    for (int idx = tid; idx < 8192; idx += 256) {
        int q = idx >> 7, d = idx & 127;
        Qs[(d << 6) + q] =
            QH[((size_t)((b << 10) + i0 + q) << 11) + (h << 7) + d];
    }
    if (tid < 64) { ms[tid] = -3.0e38f; ls[tid] = 0.f; }
    float oacc[4][8];
    #pragma unroll
    for (int a = 0; a < 4; a++)
        #pragma unroll
        for (int c = 0; c < 8; c++) oacc[a][c] = 0.f;
    __syncthreads();

    const float rscale = 0.08838834764831845f;   // 1/sqrt(128)

    for (int c = 0; c < 9; c++) {
        const int jc = i0 + (c << 6);
        // load K chunk transposed (zero fill OOB)
        for (int idx = tid; idx < 8192; idx += 256) {
            int kk = idx >> 7, d = idx & 127;
            int j = jc + kk;
            KVs[(d << 6) + kk] =
                (j < KVL) ? KH[((size_t)(b * KVL + j) << 11) + (h << 7) + d] : 0.f;
        }
        __syncthreads();

        // S = Q K^T (4x4 micro-tile per thread)
        float sacc[4][4];
        #pragma unroll
        for (int a = 0; a < 4; a++)
            #pragma unroll
            for (int e = 0; e < 4; e++) sacc[a][e] = 0.f;
        #pragma unroll 4
        for (int d = 0; d < 128; d++) {
            float4 qv = *(const float4*)&Qs[(d << 6) + qb];
            float4 kv = *(const float4*)&KVs[(d << 6) + kb];
            float qa[4] = {qv.x, qv.y, qv.z, qv.w};
            float ka[4] = {kv.x, kv.y, kv.z, kv.w};
            #pragma unroll
            for (int qi = 0; qi < 4; qi++)
                #pragma unroll
                for (int ki = 0; ki < 4; ki++)
                    sacc[qi][ki] = fmaf(qa[qi], ka[ki], sacc[qi][ki]);
        }
        #pragma unroll
        for (int qi = 0; qi < 4; qi++) {
            int i = i0 + qb + qi;
            #pragma unroll
            for (int ki = 0; ki < 4; ki++) {
                int j = jc + kb + ki;
                bool valid = (j > i) && (j <= i + WS_) && (j < KVL);
                SP[(qb + qi) * 65 + kb + ki] = valid ? sacc[qi][ki] * rscale : -1e9f;
            }
        }
        __syncthreads();

        // online softmax: warp w handles rows w*8 .. w*8+7
        {
            const int warp = tid >> 5, lane = tid & 31;
            for (int rI = 0; rI < 8; rI++) {
                int q = warp * 8 + rI;
                float v0 = SP[q * 65 + lane];
                float v1 = SP[q * 65 + 32 + lane];
                float mx = fmaxf(v0, v1);
                #pragma unroll
                for (int o = 16; o; o >>= 1)
                    mx = fmaxf(mx, __shfl_xor_sync(0xffffffffu, mx, o));
                float m_old = ms[q];
                float m_new = fmaxf(m_old, mx);
                float p0 = __expf(v0 - m_new);
                float p1 = __expf(v1 - m_new);
                float sum = p0 + p1;
                #pragma unroll
                for (int o = 16; o; o >>= 1)
                    sum += __shfl_xor_sync(0xffffffffu, sum, o);
                SP[q * 65 + lane] = p0;
                SP[q * 65 + 32 + lane] = p1;
                if (lane == 0) {
                    float sc = __expf(m_old - m_new);
                    ls[q] = ls[q] * sc + sum;
                    ms[q] = m_new;
                    osc[q] = sc;
                }
            }
        }
        __syncthreads();

        // load V chunk (natural layout) into KVs
        for (int idx = tid; idx < 8192; idx += 256) {
            int kk = idx >> 7, d = idx & 127;
            int j = jc + kk;
            KVs[idx] = (j < KVL) ? VH[((size_t)(b * KVL + j) << 11) + (h << 7) + d] : 0.f;
        }
        __syncthreads();

        // O = O*osc + P V
        #pragma unroll
        for (int qi = 0; qi < 4; qi++) {
            float sc = osc[qb + qi];
            #pragma unroll
            for (int di = 0; di < 8; di++) oacc[qi][di] *= sc;
        }
        for (int kk = 0; kk < 64; kk++) {
            float p[4];
            #pragma unroll
            for (int qi = 0; qi < 4; qi++) p[qi] = SP[(qb + qi) * 65 + kk];
            float4 va = *(const float4*)&KVs[(kk << 7) + db];
            float4 vb = *(const float4*)&KVs[(kk << 7) + db + 4];
            float vv[8] = {va.x, va.y, va.z, va.w, vb.x, vb.y, vb.z, vb.w};
            #pragma unroll
            for (int qi = 0; qi < 4; qi++)
                #pragma unroll
                for (int di = 0; di < 8; di++)
                    oacc[qi][di] = fmaf(p[qi], vv[di], oacc[qi][di]);
        }
        __syncthreads();
    }

    // write normalized output:  O[b, i, h*128+d]
    #pragma unroll
    for (int qi = 0; qi < 4; qi++) {
        float rl = 1.0f / ls[qb + qi];
        float* dst = O + ((size_t)((b << 10) + i0 + qb + qi) << 11) + (h << 7) + db;
        float4 r0 = make_float4(oacc[qi][0] * rl, oacc[qi][1] * rl,
                                oacc[qi][2] * rl, oacc[qi][3] * rl);
        float4 r1 = make_float4(oacc[qi][4] * rl, oacc[qi][5] * rl,
                                oacc[qi][6] * rl, oacc[qi][7] * rl);
        *(float4*)dst = r0;
        *(float4*)(dst + 4) = r1;
    }
}

// ---------------------------------------------------------------------------
// Host launcher
// ---------------------------------------------------------------------------
extern "C" void kernel_launch(void* const* d_in, const int* in_sizes, int n_in,
                              void* d_out, int out_size) {
    (void)in_sizes; (void)n_in; (void)out_size;
    const float* x       = (const float*)d_in[0];
    const float* cache_k = (const float*)d_in[1];
    const float* cache_v = (const float*)d_in[2];
    const float* rotary  = (const float*)d_in[3];
    const float* xscale  = (const float*)d_in[4];
    /* mask d_in[5] — band structure hardcoded */
    const float* g_in    = (const float*)d_in[6];
    const float* Wq      = (const float*)d_in[7];
    const float* Wk      = (const float*)d_in[8];
    const float* Wv      = (const float*)d_in[9];
    const float* gq      = (const float*)d_in[10];
    const float* gk      = (const float*)d_in[11];
    const float* Wlq     = (const float*)d_in[12];
    const float* blq     = (const float*)d_in[13];
    const float* Wlk     = (const float*)d_in[14];
    const float* blk     = (const float*)d_in[15];
    const float* Wlv     = (const float*)d_in[16];
    const float* blv     = (const float*)d_in[17];
    const float* Wo      = (const float*)d_in[18];
    const float* bo      = (const float*)d_in[19];
    const float* g_ffn   = (const float*)d_in[20];
    const float* W1      = (const float*)d_in[21];
    const float* W2      = (const float*)d_in[22];
    float* out = (float*)d_out;

    float *xn, *qpre, *kpre, *vnew, *qr, *kr, *vf, *qh, *kh, *vh, *ao, *op, *ln2, *ff;
    cudaGetSymbolAddress((void**)&xn,   g_xn);
    cudaGetSymbolAddress((void**)&qpre, g_qpre);
    cudaGetSymbolAddress((void**)&kpre, g_kpre);
    cudaGetSymbolAddress((void**)&vnew, g_vnew);
    cudaGetSymbolAddress((void**)&qr,   g_qr);
    cudaGetSymbolAddress((void**)&kr,   g_kr);
    cudaGetSymbolAddress((void**)&vf,   g_vf);
    cudaGetSymbolAddress((void**)&qh,   g_qh);
    cudaGetSymbolAddress((void**)&kh,   g_kh);
    cudaGetSymbolAddress((void**)&vh,   g_vh);
    cudaGetSymbolAddress((void**)&ao,   g_ao);
    cudaGetSymbolAddress((void**)&op,   g_op);
    cudaGetSymbolAddress((void**)&ln2,  g_ln2);
    cudaGetSymbolAddress((void**)&ff,   g_ff);

    static const int attn_smem = ATTN_SMEM_FLOATS * 4;
    cudaFuncSetAttribute(attn_kernel, cudaFuncAttributeMaxDynamicSharedMemorySize,
                         attn_smem);

    // 1. input LN
    ln_kernel<<<TOK, 256>>>(x, g_in, xn, DIN);

    // 2. QKV projections
    gemm_nt_kernel<<<dim3(DM_/128, TOK/128), 256>>>(xn, Wq, nullptr, qpre, TOK, DM_, DIN, 0);
    gemm_nt_kernel<<<dim3(DM_/128, TOK/128), 256>>>(xn, Wk, nullptr, kpre, TOK, DM_, DIN, 0);
    gemm_nt_kernel<<<dim3(DM_/128, TOK/128), 256>>>(xn, Wv, nullptr, vnew, TOK, DM_, DIN, 0);

    // 3. LN + RoPE + cache concat
    ln_rope_q_kernel<<<TOK, 256>>>(qpre, gq, rotary, xscale, qr);
    ln_rope_k_kernel<<<KVTOK, 256>>>(kpre, cache_k, gk, rotary, xscale, kr);
    concat_v_kernel<<<KVTOK, 256>>>(vnew, cache_v, vf);

    // 4. per-head linear projections
    gemm_nt_kernel<<<dim3(DM_/128, TOK/128),   256>>>(qr, Wlq, blq, qh, TOK,   DM_, DM_, 0);
    gemm_nt_kernel<<<dim3(DM_/128, KVTOK/128), 256>>>(kr, Wlk, blk, kh, KVTOK, DM_, DM_, 0);
    gemm_nt_kernel<<<dim3(DM_/128, KVTOK/128), 256>>>(vf, Wlv, blv, vh, KVTOK, DM_, DM_, 0);

    // 5. banded attention
    attn_kernel<<<dim3(BS_/64, B_*H_), 256, attn_smem>>>(qh, kh, vh, ao);

    // 6. output projection
    gemm_nt_kernel<<<dim3(DM_/128, TOK/128), 256>>>(ao, Wo, bo, op, TOK, DM_, DM_, 0);

    // 7. FFN: relu(LN(o) @ W1^T) @ W2^T
    ln_kernel<<<TOK, 256>>>(op, g_ffn, ln2, DM_);
    gemm_nt_kernel<<<dim3(DFF_/128, TOK/128), 256>>>(ln2, W1, nullptr, ff, TOK, DFF_, DM_, 1);
    gemm_nt_kernel<<<dim3(DIN/128,  TOK/128), 256>>>(ff,  W2, nullptr, out, TOK, DIN, DFF_, 0);
}

// round 3
// speedup vs baseline: 2.4536x; 2.4536x over previous
#include <cuda_runtime.h>
#include <cuda_bf16.h>
#include <math.h>
#include <stdint.h>

// ---------------------------------------------------------------------------
// Problem constants
// ---------------------------------------------------------------------------
#define B_   2
#define BS_  1024
#define WS_  512
#define DIN  2048
#define H_   16
#define DH_  128
#define DM_  2048
#define DFF_ 8192
#define TOK  (B_*BS_)        // 2048
#define KVL  (WS_+BS_)       // 1536
#define KVTOK (B_*KVL)       // 3072

typedef __nv_bfloat16 bf16;

// ---------------------------------------------------------------------------
// Scratch (device globals)
// ---------------------------------------------------------------------------
__device__ float g_qpre[TOK*DM_];
__device__ float g_kpre[TOK*DM_];
__device__ float g_vnew[TOK*DM_];
__device__ float g_qh  [TOK*DM_];
__device__ float g_kh  [KVTOK*DM_];
__device__ float g_vh  [KVTOK*DM_];
__device__ float g_op  [TOK*DM_];
__device__ bf16 g_xn_h [TOK*DIN],   g_xn_l [TOK*DIN];
__device__ bf16 g_qr_h [TOK*DM_],   g_qr_l [TOK*DM_];
__device__ bf16 g_kr_h [KVTOK*DM_], g_kr_l [KVTOK*DM_];
__device__ bf16 g_vf_h [KVTOK*DM_], g_vf_l [KVTOK*DM_];
__device__ bf16 g_ao_h [TOK*DM_],   g_ao_l [TOK*DM_];
__device__ bf16 g_ln2_h[TOK*DM_],   g_ln2_l[TOK*DM_];
__device__ bf16 g_ff_h [TOK*DFF_],  g_ff_l [TOK*DFF_];
__device__ bf16 g_wq_h [DM_*DIN],  g_wq_l [DM_*DIN];
__device__ bf16 g_wk_h [DM_*DIN],  g_wk_l [DM_*DIN];
__device__ bf16 g_wv_h [DM_*DIN],  g_wv_l [DM_*DIN];
__device__ bf16 g_wlq_h[DM_*DM_],  g_wlq_l[DM_*DM_];
__device__ bf16 g_wlk_h[DM_*DM_],  g_wlk_l[DM_*DM_];
__device__ bf16 g_wlv_h[DM_*DM_],  g_wlv_l[DM_*DM_];
__device__ bf16 g_wo_h [DM_*DM_],  g_wo_l [DM_*DM_];
__device__ bf16 g_w1_h [DFF_*DM_], g_w1_l [DFF_*DM_];
__device__ bf16 g_w2_h [DIN*DFF_], g_w2_l [DIN*DFF_];

// ---------------------------------------------------------------------------
// Helpers
// ---------------------------------------------------------------------------
__device__ __forceinline__ uint32_t smem_u32(const void* p) {
    uint32_t a;
    asm("{ .reg .u64 t; cvta.to.shared.u64 t, %1; cvt.u32.u64 %0, t; }"
        : "=r"(a) : "l"(p));
    return a;
}
__device__ __forceinline__ void split_store(bf16* __restrict__ h,
                                            bf16* __restrict__ l,
                                            size_t idx, float v) {
    bf16 hv = __float2bfloat16(v);
    h[idx] = hv;
    l[idx] = __float2bfloat16(v - __bfloat162float(hv));
}
__device__ __forceinline__ void cp_async16(uint32_t sa, const void* ga) {
    asm volatile("cp.async.cg.shared.global [%0], [%1], 16;"
                 :: "r"(sa), "l"(ga));
}
__device__ __forceinline__ void ldsm_x4(uint32_t* r, uint32_t addr) {
    asm volatile("ldmatrix.sync.aligned.m8n8.x4.shared.b16 {%0,%1,%2,%3}, [%4];"
                 : "=r"(r[0]), "=r"(r[1]), "=r"(r[2]), "=r"(r[3]) : "r"(addr));
}
__device__ __forceinline__ void mma16816(float* d, const uint32_t* a,
                                         const uint32_t* b) {
    asm volatile(
        "mma.sync.aligned.m16n8k16.row.col.f32.bf16.bf16.f32 "
        "{%0,%1,%2,%3}, {%4,%5,%6,%7}, {%8,%9}, {%0,%1,%2,%3};"
        : "+f"(d[0]), "+f"(d[1]), "+f"(d[2]), "+f"(d[3])
        : "r"(a[0]), "r"(a[1]), "r"(a[2]), "r"(a[3]), "r"(b[0]), "r"(b[1]));
}

// ---------------------------------------------------------------------------
// Split-bf16 HMMA GEMM:  C[M,N] = A[M,K] * B[N,K]^T  (fp32 emulated, 3 passes)
// CTA tile 128x128, BK=32, 8 warps (2m x 4n), double-buffered cp.async.
// Output: fp32 (Cf) or split hi/lo bf16 (Ch/Cl). bias/relu optional.
// ---------------------------------------------------------------------------
#define LDT     40                 // bf16 per smem row (32 + 8 pad)
#define TILE_B  (128*LDT*2)        // 10240 bytes per tile
#define STAGE_B (4*TILE_B)         // Ahi, Alo, Bhi, Blo
#define GEMM_SMEM (2*STAGE_B)      // 81920 bytes

__device__ __forceinline__ void load_chunk(uint32_t sdst, const bf16* const* g4,
                                           int c, int K, int tid) {
    #pragma unroll
    for (int m = 0; m < 4; m++) {
        const char* srcb = (const char*)(g4[m] + (size_t)c * 32);
        #pragma unroll
        for (int i = 0; i < 2; i++) {
            int u = tid + (i << 8);          // 0..511
            int row = u >> 2;
            int c16 = u & 3;
            uint32_t sa = sdst + m * TILE_B + row * (LDT * 2) + c16 * 16;
            const char* ga = srcb + (size_t)row * ((size_t)K * 2) + c16 * 16;
            cp_async16(sa, ga);
        }
    }
}

__global__ void __launch_bounds__(256) gemm_tc_kernel(
    const bf16* __restrict__ Ah, const bf16* __restrict__ Al,
    const bf16* __restrict__ Bh, const bf16* __restrict__ Bl,
    const float* __restrict__ bias,
    float* __restrict__ Cf, bf16* __restrict__ Ch, bf16* __restrict__ Cl,
    int M, int N, int K, int relu) {
    extern __shared__ char smc[];
    const uint32_t sb = smem_u32(smc);
    const int tid = threadIdx.x;
    const int bm = blockIdx.y << 7, bn = blockIdx.x << 7;
    const int warp = tid >> 5, lane = tid & 31;
    const int warpM = warp & 1;            // 0..1  (64 rows each)
    const int warpN = warp >> 1;           // 0..3  (32 cols each)

    const bf16* g4[4];
    g4[0] = Ah + (size_t)bm * K;
    g4[1] = Al + (size_t)bm * K;
    g4[2] = Bh + (size_t)bn * K;
    g4[3] = Bl + (size_t)bn * K;

    float acc[4][4][4];
    #pragma unroll
    for (int i = 0; i < 4; i++)
        #pragma unroll
        for (int j = 0; j < 4; j++)
            #pragma unroll
            for (int t = 0; t < 4; t++) acc[i][j][t] = 0.f;

    const int NC = K >> 5;
    load_chunk(sb, g4, 0, K, tid);
    asm volatile("cp.async.commit_group;");

    // precomputed ldmatrix offsets (bytes, relative to tile base)
    const int a_row = warpM * 64 + (lane & 15);
    const int a_col = (lane >> 4) << 3;            // 0 or 8
    const int b_row = warpN * 32 + (((lane >> 4) & 1) << 3) + (lane & 7);
    const int b_col = ((lane >> 3) & 1) << 3;      // 0 or 8

    for (int c = 0; c < NC; c++) {
        if (c + 1 < NC) {
            load_chunk(sb + ((c + 1) & 1) * STAGE_B, g4, c + 1, K, tid);
            asm volatile("cp.async.commit_group;");
            asm volatile("cp.async.wait_group 1;");
        } else {
            asm volatile("cp.async.wait_group 0;");
        }
        __syncthreads();

        const uint32_t st = sb + (c & 1) * STAGE_B;
        const uint32_t sAh = st, sAl = st + TILE_B;
        const uint32_t sBh = st + 2 * TILE_B, sBl = st + 3 * TILE_B;

        #pragma unroll
        for (int ks = 0; ks < 2; ks++) {
            uint32_t ah[4][4], al[4][4], bh[4][2], bl[4][2];
            const int ac = ks * 16 + a_col;
            const int bc = ks * 16 + b_col;
            #pragma unroll
            for (int im = 0; im < 4; im++) {
                uint32_t off = (uint32_t)(((a_row + im * 16) * LDT + ac) * 2);
                ldsm_x4(ah[im], sAh + off);
                ldsm_x4(al[im], sAl + off);
            }
            #pragma unroll
            for (int jp = 0; jp < 2; jp++) {
                uint32_t off = (uint32_t)(((b_row + jp * 16) * LDT + bc) * 2);
                uint32_t t[4];
                ldsm_x4(t, sBh + off);
                bh[jp * 2][0] = t[0]; bh[jp * 2][1] = t[1];
                bh[jp * 2 + 1][0] = t[2]; bh[jp * 2 + 1][1] = t[3];
                ldsm_x4(t, sBl + off);
                bl[jp * 2][0] = t[0]; bl[jp * 2][1] = t[1];
                bl[jp * 2 + 1][0] = t[2]; bl[jp * 2 + 1][1] = t[3];
            }
            #pragma unroll
            for (int im = 0; im < 4; im++)
                #pragma unroll
                for (int jn = 0; jn < 4; jn++) {
                    mma16816(acc[im][jn], ah[im], bh[jn]);
                    mma16816(acc[im][jn], ah[im], bl[jn]);
                    mma16816(acc[im][jn], al[im], bh[jn]);
                }
        }
        __syncthreads();
    }

    // epilogue
    #pragma unroll
    for (int im = 0; im < 4; im++) {
        #pragma unroll
        for (int jn = 0; jn < 4; jn++) {
            const int cc = bn + warpN * 32 + jn * 8 + ((lane & 3) << 1);
            float bia0 = 0.f, bia1 = 0.f;
            if (bias) { bia0 = __ldg(bias + cc); bia1 = __ldg(bias + cc + 1); }
            #pragma unroll
            for (int half = 0; half < 2; half++) {
                const int r = bm + warpM * 64 + im * 16 + (lane >> 2) + half * 8;
                float v0 = acc[im][jn][half * 2 + 0] + bia0;
                float v1 = acc[im][jn][half * 2 + 1] + bia1;
                if (relu) { v0 = fmaxf(v0, 0.f); v1 = fmaxf(v1, 0.f); }
                const size_t o = (size_t)r * N + cc;
                if (Cf) {
                    *(float2*)(Cf + o) = make_float2(v0, v1);
                } else {
                    bf16 h0 = __float2bfloat16(v0);
                    bf16 h1 = __float2bfloat16(v1);
                    bf16 l0 = __float2bfloat16(v0 - __bfloat162float(h0));
                    bf16 l1 = __float2bfloat16(v1 - __bfloat162float(h1));
                    bf16 hp[2] = {h0, h1}, lp[2] = {l0, l1};
                    *(uint32_t*)(Ch + o) = *(uint32_t*)hp;
                    *(uint32_t*)(Cl + o) = *(uint32_t*)lp;
                }
            }
        }
    }
}

// ---------------------------------------------------------------------------
// Weight split: fp32 -> (hi, lo) bf16
// ---------------------------------------------------------------------------
__global__ void __launch_bounds__(256) split4_kernel(const float* __restrict__ in,
                                                     bf16* __restrict__ h,
                                                     bf16* __restrict__ l, int n4) {
    int i = blockIdx.x * 256 + threadIdx.x;
    if (i >= n4) return;
    float4 v = ((const float4*)in)[i];
    bf16 hh[4], ll[4];
    float vv[4] = {v.x, v.y, v.z, v.w};
    #pragma unroll
    for (int t = 0; t < 4; t++) {
        hh[t] = __float2bfloat16(vv[t]);
        ll[t] = __float2bfloat16(vv[t] - __bfloat162float(hh[t]));
    }
    ((uint2*)h)[i] = *(uint2*)hh;
    ((uint2*)l)[i] = *(uint2*)ll;
}

// ---------------------------------------------------------------------------
// LayerNorm row stats (256 threads / row)
// ---------------------------------------------------------------------------
__device__ __forceinline__ void row_stats_256(const float* __restrict__ row, int D,
                                              float& mean, float& inv) {
    const int tid = threadIdx.x;
    float s = 0.f, s2 = 0.f;
    for (int d = tid; d < D; d += 256) {
        float v = row[d];
        s += v;
        s2 = fmaf(v, v, s2);
    }
    #pragma unroll
    for (int o = 16; o; o >>= 1) {
        s  += __shfl_xor_sync(0xffffffffu, s,  o);
        s2 += __shfl_xor_sync(0xffffffffu, s2, o);
    }
    __shared__ float ws[8], ws2[8], out2[2];
    if ((tid & 31) == 0) { ws[tid >> 5] = s; ws2[tid >> 5] = s2; }
    __syncthreads();
    if (tid == 0) {
        float a = 0.f, b2 = 0.f;
        #pragma unroll
        for (int w = 0; w < 8; w++) { a += ws[w]; b2 += ws2[w]; }
        out2[0] = a; out2[1] = b2;
    }
    __syncthreads();
    mean = out2[0] / (float)D;
    float var = out2[1] / (float)D - mean * mean;
    inv = rsqrtf(var + 1e-5f);
}

__global__ void __launch_bounds__(256) ln_split_kernel(
    const float* __restrict__ in, const float* __restrict__ g,
    bf16* __restrict__ oh, bf16* __restrict__ ol, int D) {
    const float* row = in + (size_t)blockIdx.x * D;
    size_t base = (size_t)blockIdx.x * D;
    float mean, inv;
    row_stats_256(row, D, mean, inv);
    for (int d = threadIdx.x; d < D; d += 256)
        split_store(oh, ol, base + d, (row[d] - mean) * inv * g[d]);
}

__global__ void __launch_bounds__(256) ln_rope_q_kernel(
    const float* __restrict__ in, const float* __restrict__ g,
    const float* __restrict__ rotary, const float* __restrict__ xscale,
    bf16* __restrict__ oh, bf16* __restrict__ ol) {
    const int r = blockIdx.x;
    const int i = r & (BS_ - 1);
    const int rp = WS_ + i;
    const float* row = in + (size_t)r * DM_;
    const size_t ob = (size_t)r * DM_;
    const float* fr = rotary + (size_t)rp * DM_;
    const float* sr = xscale + (size_t)rp * DM_;
    float mean, inv;
    row_stats_256(row, DM_, mean, inv);
    for (int t = threadIdx.x; t < DM_ / 2; t += 256) {
        int d0 = 2 * t;
        float x0 = (row[d0]     - mean) * inv * g[d0];
        float x1 = (row[d0 + 1] - mean) * inv * g[d0 + 1];
        float c0, s0, c1, s1;
        sincosf(fr[d0], &s0, &c0);
        sincosf(fr[d0 + 1], &s1, &c1);
        split_store(oh, ol, ob + d0,     (x0 * c0 - x1 * s0) * sr[d0]);
        split_store(oh, ol, ob + d0 + 1, (x1 * c1 + x0 * s1) * sr[d0 + 1]);
    }
}

__global__ void __launch_bounds__(256) ln_rope_k_kernel(
    const float* __restrict__ kpre, const float* __restrict__ cache_k,
    const float* __restrict__ g, const float* __restrict__ rotary,
    const float* __restrict__ xscale, bf16* __restrict__ oh, bf16* __restrict__ ol) {
    const int rr = blockIdx.x;
    const int b = rr / KVL;
    const int j = rr - b * KVL;
    const bool doln = (j >= WS_);
    const float* row = doln ? (kpre + ((size_t)b * BS_ + (j - WS_)) * DM_)
                            : (cache_k + ((size_t)b * WS_ + j) * DM_);
    float mean = 0.f, inv = 1.f;
    if (doln) row_stats_256(row, DM_, mean, inv);
    const float* fr = rotary + (size_t)j * DM_;
    const float* sr = xscale + (size_t)j * DM_;
    const size_t ob = (size_t)rr * DM_;
    for (int t = threadIdx.x; t < DM_ / 2; t += 256) {
        int d0 = 2 * t;
        float x0 = row[d0], x1 = row[d0 + 1];
        if (doln) {
            x0 = (x0 - mean) * inv * g[d0];
            x1 = (x1 - mean) * inv * g[d0 + 1];
        }
        float c0, s0, c1, s1;
        sincosf(fr[d0], &s0, &c0);
        sincosf(fr[d0 + 1], &s1, &c1);
        split_store(oh, ol, ob + d0,     (x0 * c0 - x1 * s0) / sr[d0]);
        split_store(oh, ol, ob + d0 + 1, (x1 * c1 + x0 * s1) / sr[d0 + 1]);
    }
}

__global__ void __launch_bounds__(256) concat_v_kernel(
    const float* __restrict__ vnew, const float* __restrict__ cache_v,
    bf16* __restrict__ oh, bf16* __restrict__ ol) {
    const int rr = blockIdx.x;
    const int b = rr / KVL;
    const int j = rr - b * KVL;
    const float* src = (j < WS_) ? (cache_v + ((size_t)b * WS_ + j) * DM_)
                                 : (vnew + ((size_t)b * BS_ + (j - WS_)) * DM_);
    const size_t ob = (size_t)rr * DM_;
    for (int t = threadIdx.x; t < DM_ / 4; t += 256) {
        float4 v = ((const float4*)src)[t];
        split_store(oh, ol, ob + 4 * t + 0, v.x);
        split_store(oh, ol, ob + 4 * t + 1, v.y);
        split_store(oh, ol, ob + 4 * t + 2, v.z);
        split_store(oh, ol, ob + 4 * t + 3, v.w);
    }
}

// ---------------------------------------------------------------------------
// Banded flash attention (fp32 SIMT), split bf16 output
// ---------------------------------------------------------------------------
#define ATTN_SMEM_FLOATS (8192 + 8192 + 4160 + 192)

__global__ void __launch_bounds__(256) attn_kernel(
    const float* __restrict__ QH, const float* __restrict__ KH,
    const float* __restrict__ VH, bf16* __restrict__ Oh, bf16* __restrict__ Ol) {
    extern __shared__ float sm[];
    float* Qs  = sm;
    float* KVs = sm + 8192;
    float* SP  = sm + 16384;
    float* ms  = SP + 64 * 65;
    float* ls  = ms + 64;
    float* osc = ls + 64;

    const int bh = blockIdx.y;
    const int b = bh >> 4, h = bh & 15;
    const int i0 = blockIdx.x << 6;
    const int tid = threadIdx.x;
    const int qb = (tid >> 4) << 2;
    const int kb = (tid & 15) << 2;
    const int db = (tid & 15) << 3;

    for (int idx = tid; idx < 8192; idx += 256) {
        int q = idx >> 7, d = idx & 127;
        Qs[(d << 6) + q] =
            QH[((size_t)((b << 10) + i0 + q) << 11) + (h << 7) + d];
    }
    if (tid < 64) { ms[tid] = -3.0e38f; ls[tid] = 0.f; }
    float oacc[4][8];
    #pragma unroll
    for (int a = 0; a < 4; a++)
        #pragma unroll
        for (int c = 0; c < 8; c++) oacc[a][c] = 0.f;
    __syncthreads();

    const float rscale = 0.08838834764831845f;

    for (int c = 0; c < 9; c++) {
        const int jc = i0 + (c << 6);
        for (int idx = tid; idx < 8192; idx += 256) {
            int kk = idx >> 7, d = idx & 127;
            int j = jc + kk;
            KVs[(d << 6) + kk] =
                (j < KVL) ? KH[((size_t)(b * KVL + j) << 11) + (h << 7) + d] : 0.f;
        }
        __syncthreads();

        float sacc[4][4];
        #pragma unroll
        for (int a = 0; a < 4; a++)
            #pragma unroll
            for (int e = 0; e < 4; e++) sacc[a][e] = 0.f;
        #pragma unroll 4
        for (int d = 0; d < 128; d++) {
            float4 qv = *(const float4*)&Qs[(d << 6) + qb];
            float4 kv = *(const float4*)&KVs[(d << 6) + kb];
            float qa[4] = {qv.x, qv.y, qv.z, qv.w};
            float ka[4] = {kv.x, kv.y, kv.z, kv.w};
            #pragma unroll
            for (int qi = 0; qi < 4; qi++)
                #pragma unroll
                for (int ki = 0; ki < 4; ki++)
                    sacc[qi][ki] = fmaf(qa[qi], ka[ki], sacc[qi][ki]);
        }
        #pragma unroll
        for (int qi = 0; qi < 4; qi++) {
            int i = i0 + qb + qi;
            #pragma unroll
            for (int ki = 0; ki < 4; ki++) {
                int j = jc + kb + ki;
                bool valid = (j > i) && (j <= i + WS_) && (j < KVL);
                SP[(qb + qi) * 65 + kb + ki] = valid ? sacc[qi][ki] * rscale : -1e9f;
            }
        }
        __syncthreads();

        {
            const int warp = tid >> 5, lane = tid & 31;
            for (int rI = 0; rI < 8; rI++) {
                int q = warp * 8 + rI;
                float v0 = SP[q * 65 + lane];
                float v1 = SP[q * 65 + 32 + lane];
                float mx = fmaxf(v0, v1);
                #pragma unroll
                for (int o = 16; o; o >>= 1)
                    mx = fmaxf(mx, __shfl_xor_sync(0xffffffffu, mx, o));
                float m_old = ms[q];
                float m_new = fmaxf(m_old, mx);
                float p0 = __expf(v0 - m_new);
                float p1 = __expf(v1 - m_new);
                float sum = p0 + p1;
                #pragma unroll
                for (int o = 16; o; o >>= 1)
                    sum += __shfl_xor_sync(0xffffffffu, sum, o);
                SP[q * 65 + lane] = p0;
                SP[q * 65 + 32 + lane] = p1;
                if (lane == 0) {
                    float sc = __expf(m_old - m_new);
                    ls[q] = ls[q] * sc + sum;
                    ms[q] = m_new;
                    osc[q] = sc;
                }
            }
        }
        __syncthreads();

        for (int idx = tid; idx < 8192; idx += 256) {
            int kk = idx >> 7, d = idx & 127;
            int j = jc + kk;
            KVs[idx] = (j < KVL) ? VH[((size_t)(b * KVL + j) << 11) + (h << 7) + d] : 0.f;
        }
        __syncthreads();

        #pragma unroll
        for (int qi = 0; qi < 4; qi++) {
            float sc = osc[qb + qi];
            #pragma unroll
            for (int di = 0; di < 8; di++) oacc[qi][di] *= sc;
        }
        for (int kk = 0; kk < 64; kk++) {
            float p[4];
            #pragma unroll
            for (int qi = 0; qi < 4; qi++) p[qi] = SP[(qb + qi) * 65 + kk];
            float4 va = *(const float4*)&KVs[(kk << 7) + db];
            float4 vb = *(const float4*)&KVs[(kk << 7) + db + 4];
            float vv[8] = {va.x, va.y, va.z, va.w, vb.x, vb.y, vb.z, vb.w};
            #pragma unroll
            for (int qi = 0; qi < 4; qi++)
                #pragma unroll
                for (int di = 0; di < 8; di++)
                    oacc[qi][di] = fmaf(p[qi], vv[di], oacc[qi][di]);
        }
        __syncthreads();
    }

    #pragma unroll
    for (int qi = 0; qi < 4; qi++) {
        float rl = 1.0f / ls[qb + qi];
        size_t idx = ((size_t)((b << 10) + i0 + qb + qi) << 11) + (h << 7) + db;
        #pragma unroll
        for (int di = 0; di < 8; di++)
            split_store(Oh, Ol, idx + di, oacc[qi][di] * rl);
    }
}

// ---------------------------------------------------------------------------
// Host launcher
// ---------------------------------------------------------------------------
static void gemm_tc(const bf16* Ah, const bf16* Al, const bf16* Bh, const bf16* Bl,
                    const float* bias, float* Cf, bf16* Ch, bf16* Cl,
                    int M, int N, int K, int relu) {
    gemm_tc_kernel<<<dim3(N / 128, M / 128), 256, GEMM_SMEM>>>(
        Ah, Al, Bh, Bl, bias, Cf, Ch, Cl, M, N, K, relu);
}

extern "C" void kernel_launch(void* const* d_in, const int* in_sizes, int n_in,
                              void* d_out, int out_size) {
    (void)in_sizes; (void)n_in; (void)out_size;
    const float* x       = (const float*)d_in[0];
    const float* cache_k = (const float*)d_in[1];
    const float* cache_v = (const float*)d_in[2];
    const float* rotary  = (const float*)d_in[3];
    const float* xscale  = (const float*)d_in[4];
    const float* g_in    = (const float*)d_in[6];
    const float* Wq      = (const float*)d_in[7];
    const float* Wk      = (const float*)d_in[8];
    const float* Wv      = (const float*)d_in[9];
    const float* gq      = (const float*)d_in[10];
    const float* gk      = (const float*)d_in[11];
    const float* Wlq     = (const float*)d_in[12];
    const float* blq     = (const float*)d_in[13];
    const float* Wlk     = (const float*)d_in[14];
    const float* blk     = (const float*)d_in[15];
    const float* Wlv     = (const float*)d_in[16];
    const float* blv     = (const float*)d_in[17];
    const float* Wo      = (const float*)d_in[18];
    const float* bo      = (const float*)d_in[19];
    const float* g_ffn   = (const float*)d_in[20];
    const float* W1      = (const float*)d_in[21];
    const float* W2      = (const float*)d_in[22];
    float* out = (float*)d_out;

    float *qpre, *kpre, *vnew, *qh, *kh, *vh, *op;
    cudaGetSymbolAddress((void**)&qpre, g_qpre);
    cudaGetSymbolAddress((void**)&kpre, g_kpre);
    cudaGetSymbolAddress((void**)&vnew, g_vnew);
    cudaGetSymbolAddress((void**)&qh, g_qh);
    cudaGetSymbolAddress((void**)&kh, g_kh);
    cudaGetSymbolAddress((void**)&vh, g_vh);
    cudaGetSymbolAddress((void**)&op, g_op);
    bf16 *xnh, *xnl, *qrh, *qrl, *krh, *krl, *vfh, *vfl, *aoh, *aol, *ln2h, *ln2l, *ffh, *ffl;
    cudaGetSymbolAddress((void**)&xnh, g_xn_h);  cudaGetSymbolAddress((void**)&xnl, g_xn_l);
    cudaGetSymbolAddress((void**)&qrh, g_qr_h);  cudaGetSymbolAddress((void**)&qrl, g_qr_l);
    cudaGetSymbolAddress((void**)&krh, g_kr_h);  cudaGetSymbolAddress((void**)&krl, g_kr_l);
    cudaGetSymbolAddress((void**)&vfh, g_vf_h);  cudaGetSymbolAddress((void**)&vfl, g_vf_l);
    cudaGetSymbolAddress((void**)&aoh, g_ao_h);  cudaGetSymbolAddress((void**)&aol, g_ao_l);
    cudaGetSymbolAddress((void**)&ln2h, g_ln2_h); cudaGetSymbolAddress((void**)&ln2l, g_ln2_l);
    cudaGetSymbolAddress((void**)&ffh, g_ff_h);  cudaGetSymbolAddress((void**)&ffl, g_ff_l);
    bf16 *wqh, *wql, *wkh, *wkl, *wvh, *wvl, *wlqh, *wlql, *wlkh, *wlkl, *wlvh, *wlvl,
         *woh, *wol, *w1h, *w1l, *w2h, *w2l;
    cudaGetSymbolAddress((void**)&wqh, g_wq_h);   cudaGetSymbolAddress((void**)&wql, g_wq_l);
    cudaGetSymbolAddress((void**)&wkh, g_wk_h);   cudaGetSymbolAddress((void**)&wkl, g_wk_l);
    cudaGetSymbolAddress((void**)&wvh, g_wv_h);   cudaGetSymbolAddress((void**)&wvl, g_wv_l);
    cudaGetSymbolAddress((void**)&wlqh, g_wlq_h); cudaGetSymbolAddress((void**)&wlql, g_wlq_l);
    cudaGetSymbolAddress((void**)&wlkh, g_wlk_h); cudaGetSymbolAddress((void**)&wlkl, g_wlk_l);
    cudaGetSymbolAddress((void**)&wlvh, g_wlv_h); cudaGetSymbolAddress((void**)&wlvl, g_wlv_l);
    cudaGetSymbolAddress((void**)&woh, g_wo_h);   cudaGetSymbolAddress((void**)&wol, g_wo_l);
    cudaGetSymbolAddress((void**)&w1h, g_w1_h);   cudaGetSymbolAddress((void**)&w1l, g_w1_l);
    cudaGetSymbolAddress((void**)&w2h, g_w2_h);   cudaGetSymbolAddress((void**)&w2l, g_w2_l);

    cudaFuncSetAttribute(gemm_tc_kernel, cudaFuncAttributeMaxDynamicSharedMemorySize,
                         GEMM_SMEM);
    cudaFuncSetAttribute(attn_kernel, cudaFuncAttributeMaxDynamicSharedMemorySize,
                         ATTN_SMEM_FLOATS * 4);

    auto wsplit = [](const float* w, bf16* h, bf16* l, int n) {
        int n4 = n / 4;
        split4_kernel<<<(n4 + 255) / 256, 256>>>(w, h, l, n4);
    };
    wsplit(Wq,  wqh,  wql,  DM_ * DIN);
    wsplit(Wk,  wkh,  wkl,  DM_ * DIN);
    wsplit(Wv,  wvh,  wvl,  DM_ * DIN);
    wsplit(Wlq, wlqh, wlql, DM_ * DM_);
    wsplit(Wlk, wlkh, wlkl, DM_ * DM_);
    wsplit(Wlv, wlvh, wlvl, DM_ * DM_);
    wsplit(Wo,  woh,  wol,  DM_ * DM_);
    wsplit(W1,  w1h,  w1l,  DFF_ * DM_);
    wsplit(W2,  w2h,  w2l,  DIN * DFF_);

    // 1. input LN (split)
    ln_split_kernel<<<TOK, 256>>>(x, g_in, xnh, xnl, DIN);

    // 2. QKV projections
    gemm_tc(xnh, xnl, wqh, wql, nullptr, qpre, nullptr, nullptr, TOK, DM_, DIN, 0);
    gemm_tc(xnh, xnl, wkh, wkl, nullptr, kpre, nullptr, nullptr, TOK, DM_, DIN, 0);
    gemm_tc(xnh, xnl, wvh, wvl, nullptr, vnew, nullptr, nullptr, TOK, DM_, DIN, 0);

    // 3. LN + RoPE + concat (split outputs)
    ln_rope_q_kernel<<<TOK, 256>>>(qpre, gq, rotary, xscale, qrh, qrl);
    ln_rope_k_kernel<<<KVTOK, 256>>>(kpre, cache_k, gk, rotary, xscale, krh, krl);
    concat_v_kernel<<<KVTOK, 256>>>(vnew, cache_v, vfh, vfl);

    // 4. head projections
    gemm_tc(qrh, qrl, wlqh, wlql, blq, qh, nullptr, nullptr, TOK,   DM_, DM_, 0);
    gemm_tc(krh, krl, wlkh, wlkl, blk, kh, nullptr, nullptr, KVTOK, DM_, DM_, 0);
    gemm_tc(vfh, vfl, wlvh, wlvl, blv, vh, nullptr, nullptr, KVTOK, DM_, DM_, 0);

    // 5. banded attention (split output)
    attn_kernel<<<dim3(BS_ / 64, B_ * H_), 256, ATTN_SMEM_FLOATS * 4>>>(qh, kh, vh, aoh, aol);

    // 6. output projection
    gemm_tc(aoh, aol, woh, wol, bo, op, nullptr, nullptr, TOK, DM_, DM_, 0);

    // 7. FFN
    ln_split_kernel<<<TOK, 256>>>(op, g_ffn, ln2h, ln2l, DM_);
    gemm_tc(ln2h, ln2l, w1h, w1l, nullptr, nullptr, ffh, ffl, TOK, DFF_, DM_, 1);
    gemm_tc(ffh, ffl, w2h, w2l, nullptr, out, nullptr, nullptr, TOK, DIN, DFF_, 0);
}